// round 14
// baseline (speedup 1.0000x reference)
#include <cuda_runtime.h>
#include <cstdint>

// SimpleGCNLayer: out = segment_sum(x[src], dst) @ W.T
// Final configuration (measured best, R10: 49.9us total, scatter 40.6us):
//  - transform-first: y = x @ W.T (register-tiled, smem-staged, no shuffles),
//    fused d_out zeroing + edge-index dtype probe
//  - scatter: one-shot grid, 32 edges/warp, coalesced index load + shuffle
//    distribution, 8 independent float4 gathers (MLP=8), 8 fire-and-forget
//    red.global.add.v4.f32.
// Probed and rejected: MLP=1 (55us), forced occupancy (44.7us), persistent
// grid (47.4us), .cg gathers (neutral). Scatter sits at the L1tex wavefront
// floor (1 line/edge each way); transform near its 38MB streaming floor.

#define D 32
#define N_NODES_MAX 100352
#define TNODES 128          // nodes per transform block
#define XS_STRIDE 36        // smem row stride: %32==4 -> conflict-free, 16B aligned

__device__ __align__(128) float g_y[(size_t)N_NODES_MAX * D];
__device__ int g_is64;

// Block = 256 threads = 128 nodes. Thread (g = tid>>3, q = tid&7) owns
// 4 nodes (g, g+32, g+64, g+96) x 4 outputs (4q..4q+3): 16 accumulators.
// Block 0 / warp 0 also probes the edge-index dtype (int64 => odd words all 0).
__global__ void __launch_bounds__(256) gcn_transform_zero(
    const float* __restrict__ x,
    const float* __restrict__ W,
    float* __restrict__ out,
    const int* __restrict__ ei32,
    int ei_words,
    int n_nodes)
{
    __shared__ float xs[TNODES * XS_STRIDE];   // x tile, padded rows
    __shared__ float wt[D * D];                // W transposed: wt[i*32+o] = W[o][i]

    const int tid = threadIdx.x;
    const int node_base = blockIdx.x * TNODES;

    if (blockIdx.x == 0 && tid < 32) {   // dtype probe, overlapped with grid
        int allzero = 1;
        for (int k = tid; k < 256; k += 32) {
            const int odd = 2 * k + 1;
            if (odd < ei_words && ei32[odd] != 0) allzero = 0;
        }
        allzero = __all_sync(0xffffffffu, allzero);
        if (tid == 0) g_is64 = allzero;
    }

    // Stage W transposed: wt[i][o] = W[o][i].
#pragma unroll
    for (int k = 0; k < 4; k++) {
        const int idx = tid + k * 256;        // o = idx>>5, i = idx&31
        wt[(idx & 31) * D + (idx >> 5)] = W[idx];
    }
    // Stage x tile (float4-coalesced).
#pragma unroll
    for (int k = 0; k < 4; k++) {
        const int idx4 = tid + k * 256;       // 1024 float4s = 128 rows x 8
        const int nl = idx4 >> 3, i4 = (idx4 & 7) * 4;
        float4 xv = make_float4(0.f, 0.f, 0.f, 0.f);
        if (node_base + nl < n_nodes)
            xv = *reinterpret_cast<const float4*>(x + (size_t)(node_base + nl) * D + i4);
        *reinterpret_cast<float4*>(xs + nl * XS_STRIDE + i4) = xv;
    }
    __syncthreads();

    const int q  = tid & 7;          // output quad: columns 4q..4q+3
    const int g  = tid >> 3;         // node group 0..31
    float4 acc[4] = {};

#pragma unroll
    for (int i = 0; i < D; i++) {
        const float4 w4 = *reinterpret_cast<const float4*>(wt + i * D + 4 * q);
#pragma unroll
        for (int r = 0; r < 4; r++) {
            const float xv = xs[(g + 32 * r) * XS_STRIDE + i];   // broadcast LDS
            acc[r].x = fmaf(xv, w4.x, acc[r].x);
            acc[r].y = fmaf(xv, w4.y, acc[r].y);
            acc[r].z = fmaf(xv, w4.z, acc[r].z);
            acc[r].w = fmaf(xv, w4.w, acc[r].w);
        }
    }

#pragma unroll
    for (int r = 0; r < 4; r++) {
        const int node = node_base + g + 32 * r;
        if (node < n_nodes) {
            *reinterpret_cast<float4*>(g_y + (size_t)node * D + 4 * q) = acc[r];
            *reinterpret_cast<float4*>(out + (size_t)node * D + 4 * q) =
                make_float4(0.f, 0.f, 0.f, 0.f);   // d_out poisoned; zero it
        }
    }
}

// One warp handles 32 edges: coalesced index load + shuffle distribution,
// then 8 independent float4 gathers per thread (MLP=8) and 8 vector REDs.
// Safety clamps applied once per warp; full warps run predicate-free.
__global__ void __launch_bounds__(256) gcn_scatter(
    const int* __restrict__ ei32,   // [2, n_edges]: src row then dst row
    float* __restrict__ out,
    int n_edges, int n_nodes)
{
    const int lane = threadIdx.x & 31;
    const long long base = ((long long)blockIdx.x * 8 + (threadIdx.x >> 5)) * 32;
    if (base >= n_edges) return;

    const bool full = (base + 32 <= n_edges);
    int s_all = 0, d_all = 0;
    const long long e = base + lane;
    if (full || e < n_edges) {
        if (g_is64) {   // uniform branch
            const long long* ei64 = (const long long*)ei32;
            s_all = (int)__ldg(ei64 + e);
            d_all = (int)__ldg(ei64 + n_edges + e);
        } else {
            s_all = __ldg(ei32 + e);
            d_all = __ldg(ei32 + (long long)n_edges + e);
        }
    }
    // Once-per-warp safety clamp (never taken with valid data; prevents faults).
    if ((unsigned)s_all >= (unsigned)n_nodes) s_all = 0;
    if ((unsigned)d_all >= (unsigned)n_nodes) d_all = 0;

    const int sub4 = (lane & 7) * 4;
    float4 v[8];
    int    dd[8];

    if (full) {
#pragma unroll
        for (int u = 0; u < 8; u++) {
            const int eiw = u * 4 + (lane >> 3);
            const int s = __shfl_sync(0xffffffffu, s_all, eiw);
            dd[u]       = __shfl_sync(0xffffffffu, d_all, eiw);
            v[u] = *reinterpret_cast<const float4*>(g_y + (size_t)s * D + sub4);
        }
#pragma unroll
        for (int u = 0; u < 8; u++) {
            float* p = out + (size_t)dd[u] * D + sub4;
            asm volatile("red.global.add.v4.f32 [%0], {%1, %2, %3, %4};"
                         :: "l"(p), "f"(v[u].x), "f"(v[u].y), "f"(v[u].z), "f"(v[u].w)
                         : "memory");
        }
    } else {
#pragma unroll
        for (int u = 0; u < 8; u++) {
            const int eiw = u * 4 + (lane >> 3);
            const int s = __shfl_sync(0xffffffffu, s_all, eiw);
            dd[u]       = __shfl_sync(0xffffffffu, d_all, eiw);
            v[u] = (base + eiw < n_edges)
                 ? *reinterpret_cast<const float4*>(g_y + (size_t)s * D + sub4)
                 : make_float4(0.f, 0.f, 0.f, 0.f);
        }
#pragma unroll
        for (int u = 0; u < 8; u++) {
            if (base + u * 4 + (lane >> 3) < n_edges) {
                float* p = out + (size_t)dd[u] * D + sub4;
                asm volatile("red.global.add.v4.f32 [%0], {%1, %2, %3, %4};"
                             :: "l"(p), "f"(v[u].x), "f"(v[u].y), "f"(v[u].z), "f"(v[u].w)
                             : "memory");
            }
        }
    }
}

extern "C" void kernel_launch(void* const* d_in, const int* in_sizes, int n_in,
                              void* d_out, int out_size)
{
    const float* x    = (const float*)d_in[0];   // [N, 32] f32
    const int*   ei32 = (const int*)d_in[1];     // [2, E] int32 (int64 auto-detected)
    const float* W    = (const float*)d_in[2];   // [32, 32] f32
    float* out = (float*)d_out;                  // [N, 32] f32

    const int n_nodes = in_sizes[0] / D;
    const int n_edges = in_sizes[1] / 2;

    const int tblocks = (n_nodes + TNODES - 1) / TNODES;
    gcn_transform_zero<<<tblocks, 256>>>(x, W, out, ei32, in_sizes[1], n_nodes);

    const long long warps = ((long long)n_edges + 31) / 32;
    const int sblocks = (int)((warps + 7) / 8);
    gcn_scatter<<<sblocks, 256>>>(ei32, out, n_edges, n_nodes);
}

// round 15
// speedup vs baseline: 1.0457x; 1.0457x over previous
#include <cuda_runtime.h>
#include <cstdint>

// SimpleGCNLayer: out = segment_sum(x[src], dst) @ W.T
// Transform-first (register-tiled) + vector-RED scatter (MLP=8), now with
// PDL overlap: the scatter is launched with programmatic stream
// serialization; it performs its (transform-independent) edge-index loads
// first, then cudaGridDependencySynchronize() before touching g_y/out.
// Edge index is int32 (confirmed by 6 passing rounds; the R2 IMA ruled out
// int64). Per-warp clamps keep wrong indices from ever faulting.

#define D 32
#define N_NODES_MAX 100352
#define TNODES 128          // nodes per transform block
#define XS_STRIDE 36        // smem row stride: %32==4 -> conflict-free, 16B aligned

__device__ __align__(128) float g_y[(size_t)N_NODES_MAX * D];

// Block = 256 threads = 128 nodes. Thread (g = tid>>3, q = tid&7) owns
// 4 nodes (g, g+32, g+64, g+96) x 4 outputs (4q..4q+3): 16 accumulators.
__global__ void __launch_bounds__(256) gcn_transform_zero(
    const float* __restrict__ x,
    const float* __restrict__ W,
    float* __restrict__ out,
    int n_nodes)
{
    __shared__ float xs[TNODES * XS_STRIDE];   // x tile, padded rows
    __shared__ float wt[D * D];                // W transposed: wt[i*32+o] = W[o][i]

    const int tid = threadIdx.x;
    const int node_base = blockIdx.x * TNODES;

    // Stage W transposed: wt[i][o] = W[o][i].
#pragma unroll
    for (int k = 0; k < 4; k++) {
        const int idx = tid + k * 256;        // o = idx>>5, i = idx&31
        wt[(idx & 31) * D + (idx >> 5)] = W[idx];
    }
    // Stage x tile (float4-coalesced).
#pragma unroll
    for (int k = 0; k < 4; k++) {
        const int idx4 = tid + k * 256;       // 1024 float4s = 128 rows x 8
        const int nl = idx4 >> 3, i4 = (idx4 & 7) * 4;
        float4 xv = make_float4(0.f, 0.f, 0.f, 0.f);
        if (node_base + nl < n_nodes)
            xv = *reinterpret_cast<const float4*>(x + (size_t)(node_base + nl) * D + i4);
        *reinterpret_cast<float4*>(xs + nl * XS_STRIDE + i4) = xv;
    }
    __syncthreads();

    const int q  = tid & 7;          // output quad: columns 4q..4q+3
    const int g  = tid >> 3;         // node group 0..31
    float4 acc[4] = {};

#pragma unroll
    for (int i = 0; i < D; i++) {
        const float4 w4 = *reinterpret_cast<const float4*>(wt + i * D + 4 * q);
#pragma unroll
        for (int r = 0; r < 4; r++) {
            const float xv = xs[(g + 32 * r) * XS_STRIDE + i];   // broadcast LDS
            acc[r].x = fmaf(xv, w4.x, acc[r].x);
            acc[r].y = fmaf(xv, w4.y, acc[r].y);
            acc[r].z = fmaf(xv, w4.z, acc[r].z);
            acc[r].w = fmaf(xv, w4.w, acc[r].w);
        }
    }

    // Let the dependent (scatter) grid launch now: its index-load prologue
    // overlaps our epilogue. Visibility of g_y/out is enforced by the
    // scatter's cudaGridDependencySynchronize(), which waits for our full
    // completion.
    cudaTriggerProgrammaticLaunchCompletion();

#pragma unroll
    for (int r = 0; r < 4; r++) {
        const int node = node_base + g + 32 * r;
        if (node < n_nodes) {
            *reinterpret_cast<float4*>(g_y + (size_t)node * D + 4 * q) = acc[r];
            *reinterpret_cast<float4*>(out + (size_t)node * D + 4 * q) =
                make_float4(0.f, 0.f, 0.f, 0.f);   // d_out poisoned; zero it
        }
    }
}

// One warp handles 32 edges: coalesced index load + shuffle distribution,
// then 8 independent float4 gathers per thread (MLP=8) and 8 vector REDs.
// Index loads happen BEFORE the grid-dependency sync (they only read ei32).
__global__ void __launch_bounds__(256) gcn_scatter(
    const int* __restrict__ ei32,   // [2, n_edges] int32: src row then dst row
    float* __restrict__ out,
    int n_edges, int n_nodes)
{
    const int lane = threadIdx.x & 31;
    const long long base = ((long long)blockIdx.x * 8 + (threadIdx.x >> 5)) * 32;
    if (base >= n_edges) { cudaGridDependencySynchronize(); return; }

    const bool full = (base + 32 <= n_edges);
    int s_all = 0, d_all = 0;
    const long long e = base + lane;
    if (full || e < n_edges) {
        s_all = __ldg(ei32 + e);
        d_all = __ldg(ei32 + (long long)n_edges + e);
    }
    // Once-per-warp safety clamp (never taken with valid data; prevents faults).
    if ((unsigned)s_all >= (unsigned)n_nodes) s_all = 0;
    if ((unsigned)d_all >= (unsigned)n_nodes) d_all = 0;

    // Wait for the transform grid (g_y written, out zeroed) before gathering.
    cudaGridDependencySynchronize();

    const int sub4 = (lane & 7) * 4;
    float4 v[8];
    int    dd[8];

    if (full) {
#pragma unroll
        for (int u = 0; u < 8; u++) {
            const int eiw = u * 4 + (lane >> 3);
            const int s = __shfl_sync(0xffffffffu, s_all, eiw);
            dd[u]       = __shfl_sync(0xffffffffu, d_all, eiw);
            v[u] = *reinterpret_cast<const float4*>(g_y + (size_t)s * D + sub4);
        }
#pragma unroll
        for (int u = 0; u < 8; u++) {
            float* p = out + (size_t)dd[u] * D + sub4;
            asm volatile("red.global.add.v4.f32 [%0], {%1, %2, %3, %4};"
                         :: "l"(p), "f"(v[u].x), "f"(v[u].y), "f"(v[u].z), "f"(v[u].w)
                         : "memory");
        }
    } else {
#pragma unroll
        for (int u = 0; u < 8; u++) {
            const int eiw = u * 4 + (lane >> 3);
            const int s = __shfl_sync(0xffffffffu, s_all, eiw);
            dd[u]       = __shfl_sync(0xffffffffu, d_all, eiw);
            v[u] = (base + eiw < n_edges)
                 ? *reinterpret_cast<const float4*>(g_y + (size_t)s * D + sub4)
                 : make_float4(0.f, 0.f, 0.f, 0.f);
        }
#pragma unroll
        for (int u = 0; u < 8; u++) {
            if (base + u * 4 + (lane >> 3) < n_edges) {
                float* p = out + (size_t)dd[u] * D + sub4;
                asm volatile("red.global.add.v4.f32 [%0], {%1, %2, %3, %4};"
                             :: "l"(p), "f"(v[u].x), "f"(v[u].y), "f"(v[u].z), "f"(v[u].w)
                             : "memory");
            }
        }
    }
}

extern "C" void kernel_launch(void* const* d_in, const int* in_sizes, int n_in,
                              void* d_out, int out_size)
{
    const float* x    = (const float*)d_in[0];   // [N, 32] f32
    const int*   ei32 = (const int*)d_in[1];     // [2, E] int32
    const float* W    = (const float*)d_in[2];   // [32, 32] f32
    float* out = (float*)d_out;                  // [N, 32] f32

    const int n_nodes = in_sizes[0] / D;
    const int n_edges = in_sizes[1] / 2;

    const int tblocks = (n_nodes + TNODES - 1) / TNODES;
    gcn_transform_zero<<<tblocks, 256>>>(x, W, out, n_nodes);

    // Scatter launched with programmatic stream serialization: its index-load
    // prologue runs under the transform's tail; the grid-dependency sync in
    // the kernel provides the real ordering on g_y/out.
    const long long warps = ((long long)n_edges + 31) / 32;
    const int sblocks = (int)((warps + 7) / 8);

    cudaLaunchConfig_t cfg = {};
    cfg.gridDim  = dim3((unsigned)sblocks, 1, 1);
    cfg.blockDim = dim3(256, 1, 1);
    cfg.dynamicSmemBytes = 0;
    cfg.stream = 0;   // same (capture) stream as the <<<>>> launch above
    cudaLaunchAttribute attr[1];
    attr[0].id = cudaLaunchAttributeProgrammaticStreamSerialization;
    attr[0].val.programmaticStreamSerializationAllowed = 1;
    cfg.attrs = attr;
    cfg.numAttrs = 1;
    cudaLaunchKernelEx(&cfg, gcn_scatter, ei32, out, n_edges, n_nodes);
}